// round 11
// baseline (speedup 1.0000x reference)
#include <cuda_runtime.h>
#include <cuda_fp16.h>
#include <cstdint>

#define B_SZ 8192
#define L_SZ 64
#define EMB  64
#define HID  128
#define G3   384
#define OUTD 128
#define NVAL 1000

__device__ float g_tab[NVAL * G3];      // xg table, PERMUTED within 16-chunks (fp32, L2-hot)
__device__ float g_Wih_t[EMB * G3];
__device__ float g_cbias[G3];
__device__ uint32_t g_Bf[8 * 8 * 32 * 12];  // Whh fp16 B-fragments, 96KB
__device__ uint32_t g_Of[8 * 32 * 32];      // Wout fp16 B-fragments, 32KB

__device__ __forceinline__ float ftanh_fast(float x) {
    float r;
    asm("tanh.approx.f32 %0, %1;" : "=f"(r) : "f"(x));
    return r;
}
__device__ __forceinline__ float fsig_fast(float x) {
    return fmaf(0.5f, ftanh_fast(0.5f * x), 0.5f);
}
__device__ __forceinline__ uint32_t packh2(float lo, float hi) {
    __half2 h = __floats2half2_rn(lo, hi);
    return *reinterpret_cast<uint32_t*>(&h);
}
__device__ __forceinline__ void hmma(float* d, const uint32_t* a, uint32_t b0, uint32_t b1) {
    asm volatile("mma.sync.aligned.m16n8k16.row.col.f32.f16.f16.f32 "
        "{%0,%1,%2,%3}, {%4,%5,%6,%7}, {%8,%9}, {%0,%1,%2,%3};"
        : "+f"(d[0]), "+f"(d[1]), "+f"(d[2]), "+f"(d[3])
        : "r"(a[0]), "r"(a[1]), "r"(a[2]), "r"(a[3]), "r"(b0), "r"(b1));
}
__device__ __forceinline__ int pperm(int o) {
    return 4 * ((o & 7) >> 1) + (((o >> 3) & 1) << 1) + (o & 1);
}

// ---------------- prep: fragment images ----------------
__global__ void prep_kernel(const float* __restrict__ Wih, const float* __restrict__ Whh,
                            const float* __restrict__ bih, const float* __restrict__ bhh,
                            const float* __restrict__ Wout) {
    int i = blockIdx.x * blockDim.x + threadIdx.x;
    if (i < EMB * G3) { int k = i / G3, gj = i % G3; g_Wih_t[i] = Wih[gj * EMB + k]; }
    if (i < G3) g_cbias[i] = bih[i] + (i < 2 * HID ? bhh[i] : 0.0f);
    if (i < G3 * HID) {
        int gj = i / HID, k = i % HID;
        uint16_t hb = __half_as_ushort(__float2half_rn(Whh[i]));
        int gate = gj >> 7, jr = gj & 127;
        int jc = jr >> 4, nt = (jr >> 3) & 1, nl = jr & 7;
        int kc = k >> 4, kk = k & 15;
        int breg = kk >> 3, q = (kk & 7) >> 1, hs = kk & 1;
        int T = nl * 4 + q, f = gate * 2 + nt;
        int u = ((jc * 8 + kc) * 32 + T) * 12 + f * 2 + breg;
        ((uint16_t*)g_Bf)[u * 2 + hs] = hb;
    }
    if (i < OUTD * HID) {
        int o = i / HID, k = i % HID;
        uint16_t hb = __half_as_ushort(__float2half_rn(Wout[i]));
        int f = o >> 3, nl = o & 7;
        int kc = k >> 4, kk = k & 15;
        int breg = kk >> 3, q = (kk & 7) >> 1, hs = kk & 1;
        int T = nl * 4 + q;
        int u = (kc * 32 + T) * 32 + f * 2 + breg;
        ((uint16_t*)g_Of)[u * 2 + hs] = hb;
    }
}

__global__ void table_kernel(const float* __restrict__ embed) {
    __shared__ float es[EMB];
    const int v = blockIdx.x, gj = threadIdx.x;
    if (gj < EMB) es[gj] = embed[v * EMB + gj];
    __syncthreads();
    float acc = 0.0f;
    #pragma unroll 8
    for (int k = 0; k < EMB; k++) acc = fmaf(es[k], g_Wih_t[k * G3 + gj], acc);
    const int gate = gj >> 7, rest = gj & 127, chunk = rest >> 4, o = rest & 15;
    g_tab[v * G3 + gate * 128 + chunk * 16 + pperm(o)] = acc + g_cbias[gj];
}

// ---------------- GRU: jc-skewed MMA/epilogue pipeline, SMEM-parked An ----------------
#define GRU_SMEM (131072 + 512 + 16384)
__global__ __launch_bounds__(128, 1) void gru_kernel(const int* __restrict__ x,
                                                     const float* __restrict__ bhh,
                                                     const float* __restrict__ bout,
                                                     float* __restrict__ out) {
    extern __shared__ uint32_t sm[];
    uint32_t* Bs = sm;                      // 24576 u32
    uint32_t* Os = sm + 24576;              // 8192 u32
    float* bns = (float*)(sm + 32768);      // 128 floats, permuted bhh_n
    const int tid = threadIdx.x;
    uint4* AnPark = (uint4*)(sm + 32896) + tid * 8;   // 8 uint4 per thread (warp-private)
    {
        uint4* d = (uint4*)sm;
        const uint4* s1 = (const uint4*)g_Bf;
        for (int i = tid; i < 6144; i += 128) d[i] = s1[i];
        const uint4* s2 = (const uint4*)g_Of;
        for (int i = tid; i < 2048; i += 128) d[6144 + i] = s2[i];
    }
    if (tid < 128) {
        int o = tid & 15, chunk = tid >> 4;
        bns[chunk * 16 + pperm(o)] = bhh[256 + tid];
    }
    __syncthreads();

    const int w = tid >> 5, T = tid & 31;
    const int g = T >> 2, a4 = (T & 3) * 4;
    const int rowA = blockIdx.x * 64 + w * 16 + g;
    const int rowB = rowA + 8;
    const float* __restrict__ tab = g_tab;

    uint32_t A[32];
    float hp[64];
    #pragma unroll
    for (int i = 0; i < 32; i++) A[i] = 0u;
    #pragma unroll
    for (int i = 0; i < 64; i++) hp[i] = 0.0f;

    int idxA = x[rowA * L_SZ], idxB = x[rowB * L_SZ];
    const float* tA = tab + (size_t)idxA * G3 + a4;
    const float* tB = tab + (size_t)idxB * G3 + a4;

    // xg current-chunk registers (seed source); preload chunk 0 of step 0
    float4 crA = __ldg((const float4*)(tA));
    float4 crB = __ldg((const float4*)(tB));
    float4 czA = __ldg((const float4*)(tA + 128));
    float4 czB = __ldg((const float4*)(tB + 128));
    float4 cnA = __ldg((const float4*)(tA + 256));
    float4 cnB = __ldg((const float4*)(tB + 256));

    float d0[6][4], d1[6][4];
    float4 pnA0, pnB0, pnA1, pnB1;   // saved xn per parity slot

// seed accumulators with gate offsets, save xn, prefetch next chunk, issue 48 HMMA
#define SEED_MMA(DC, PNA, PNB, JC) do {                                          \
    float4 bn4 = *(const float4*)(bns + (JC) * 16 + a4);                         \
    DC[0][0]=crA.x; DC[0][1]=crA.y; DC[0][2]=crB.x; DC[0][3]=crB.y;              \
    DC[1][0]=crA.z; DC[1][1]=crA.w; DC[1][2]=crB.z; DC[1][3]=crB.w;              \
    DC[2][0]=czA.x; DC[2][1]=czA.y; DC[2][2]=czB.x; DC[2][3]=czB.y;              \
    DC[3][0]=czA.z; DC[3][1]=czA.w; DC[3][2]=czB.z; DC[3][3]=czB.w;              \
    DC[4][0]=bn4.x; DC[4][1]=bn4.y; DC[4][2]=bn4.x; DC[4][3]=bn4.y;              \
    DC[5][0]=bn4.z; DC[5][1]=bn4.w; DC[5][2]=bn4.z; DC[5][3]=bn4.w;              \
    PNA = cnA; PNB = cnB;                                                        \
    if ((JC) < 7) {                                                              \
        const int jn = ((JC) + 1) * 16;                                          \
        crA = __ldg((const float4*)(tA + jn));                                   \
        crB = __ldg((const float4*)(tB + jn));                                   \
        czA = __ldg((const float4*)(tA + 128 + jn));                             \
        czB = __ldg((const float4*)(tB + 128 + jn));                             \
        cnA = __ldg((const float4*)(tA + 256 + jn));                             \
        cnB = __ldg((const float4*)(tB + 256 + jn));                             \
    } else {                                                                     \
        tA = tab + (size_t)idxA2 * G3 + a4;                                      \
        tB = tab + (size_t)idxB2 * G3 + a4;                                      \
        crA = __ldg((const float4*)(tA));                                        \
        crB = __ldg((const float4*)(tB));                                        \
        czA = __ldg((const float4*)(tA + 128));                                  \
        czB = __ldg((const float4*)(tB + 128));                                  \
        cnA = __ldg((const float4*)(tA + 256));                                  \
        cnB = __ldg((const float4*)(tB + 256));                                  \
    }                                                                            \
    _Pragma("unroll")                                                            \
    for (int kc = 0; kc < 8; kc++) {                                             \
        const uint4* bp = (const uint4*)(Bs + (((JC) * 8 + kc) * 32 + T) * 12);  \
        uint4 b0 = bp[0], b1 = bp[1], b2 = bp[2];                                \
        hmma(DC[0], &A[kc * 4], b0.x, b0.y);                                     \
        hmma(DC[1], &A[kc * 4], b0.z, b0.w);                                     \
        hmma(DC[2], &A[kc * 4], b1.x, b1.y);                                     \
        hmma(DC[3], &A[kc * 4], b1.z, b1.w);                                     \
        hmma(DC[4], &A[kc * 4], b2.x, b2.y);                                     \
        hmma(DC[5], &A[kc * 4], b2.z, b2.w);                                     \
    }                                                                            \
} while (0)

// gate epilogue for chunk JC using accumulators DP and saved xn
#define EPI(DP, PNA, PNB, JC) do {                                               \
    float xn[8] = {PNA.x, PNA.y, PNB.x, PNB.y, PNA.z, PNA.w, PNB.z, PNB.w};      \
    float hv[8];                                                                 \
    _Pragma("unroll")                                                            \
    for (int u = 0; u < 8; u++) {                                                \
        int nt = u >> 2, pos = u & 3;                                            \
        float r = fsig_fast(DP[nt][pos]);                                        \
        float z = fsig_fast(DP[2 + nt][pos]);                                    \
        float n = ftanh_fast(fmaf(r, DP[4 + nt][pos], xn[u]));                   \
        float h = fmaf(z, hp[(JC) * 8 + u] - n, n);                              \
        hp[(JC) * 8 + u] = h;                                                    \
        hv[u] = h;                                                               \
    }                                                                            \
    AnPark[JC] = make_uint4(packh2(hv[0], hv[1]), packh2(hv[2], hv[3]),          \
                            packh2(hv[4], hv[5]), packh2(hv[6], hv[7]));         \
} while (0)

    #pragma unroll 1
    for (int t = 0; t < L_SZ; t++) {
        int idxA2 = idxA, idxB2 = idxB;
        if (t + 1 < L_SZ) {
            idxA2 = x[rowA * L_SZ + t + 1];
            idxB2 = x[rowB * L_SZ + t + 1];
        }
        // skewed pipeline: HMMA(jc+1) issues before epilogue(jc)
        SEED_MMA(d0, pnA0, pnB0, 0);
        SEED_MMA(d1, pnA1, pnB1, 1);  EPI(d0, pnA0, pnB0, 0);
        SEED_MMA(d0, pnA0, pnB0, 2);  EPI(d1, pnA1, pnB1, 1);
        SEED_MMA(d1, pnA1, pnB1, 3);  EPI(d0, pnA0, pnB0, 2);
        SEED_MMA(d0, pnA0, pnB0, 4);  EPI(d1, pnA1, pnB1, 3);
        SEED_MMA(d1, pnA1, pnB1, 5);  EPI(d0, pnA0, pnB0, 4);
        SEED_MMA(d0, pnA0, pnB0, 6);  EPI(d1, pnA1, pnB1, 5);
        SEED_MMA(d1, pnA1, pnB1, 7);  EPI(d0, pnA0, pnB0, 6);
                                      EPI(d1, pnA1, pnB1, 7);
        // reload A fragments from parked An (thread-private SMEM, no sync)
        #pragma unroll
        for (int c = 0; c < 8; c++) {
            uint4 v = AnPark[c];
            A[c * 4 + 0] = v.x; A[c * 4 + 1] = v.y;
            A[c * 4 + 2] = v.z; A[c * 4 + 3] = v.w;
        }
        idxA = idxA2; idxB = idxB2;
    }

    // output projection: out = h @ Wout^T + bout
    float od[16][4];
    #pragma unroll
    for (int f = 0; f < 16; f++)
        #pragma unroll
        for (int p = 0; p < 4; p++) od[f][p] = 0.0f;
    #pragma unroll
    for (int kc = 0; kc < 8; kc++) {
        const uint4* op = (const uint4*)(Os + (kc * 32 + T) * 32);
        #pragma unroll
        for (int f2 = 0; f2 < 8; f2++) {
            uint4 v = op[f2];
            hmma(od[f2 * 2 + 0], &A[kc * 4], v.x, v.y);
            hmma(od[f2 * 2 + 1], &A[kc * 4], v.z, v.w);
        }
    }
    const int q2 = (T & 3) * 2;
    #pragma unroll
    for (int f = 0; f < 16; f++) {
        float2 bo = *(const float2*)(bout + f * 8 + q2);
        float2 oA = make_float2(od[f][0] + bo.x, od[f][1] + bo.y);
        float2 oB = make_float2(od[f][2] + bo.x, od[f][3] + bo.y);
        *(float2*)(out + (size_t)rowA * OUTD + f * 8 + q2) = oA;
        *(float2*)(out + (size_t)rowB * OUTD + f * 8 + q2) = oB;
    }
}

extern "C" void kernel_launch(void* const* d_in, const int* in_sizes, int n_in,
                              void* d_out, int out_size) {
    const int*   x     = (const int*)d_in[0];
    const float* embed = (const float*)d_in[1];
    const float* Wih   = (const float*)d_in[2];
    const float* Whh   = (const float*)d_in[3];
    const float* bih   = (const float*)d_in[4];
    const float* bhh   = (const float*)d_in[5];
    const float* Wout  = (const float*)d_in[6];
    const float* bout  = (const float*)d_in[7];
    float* out = (float*)d_out;

    static bool attr_done = false;
    if (!attr_done) {
        cudaFuncSetAttribute(gru_kernel, cudaFuncAttributeMaxDynamicSharedMemorySize, GRU_SMEM);
        attr_done = true;
    }

    prep_kernel<<<192, 256>>>(Wih, Whh, bih, bhh, Wout);
    table_kernel<<<NVAL, G3>>>(embed);
    gru_kernel<<<B_SZ / 64, 128, GRU_SMEM>>>(x, bhh, bout, out);
}

// round 12
// speedup vs baseline: 1.2510x; 1.2510x over previous
#include <cuda_runtime.h>
#include <cuda_fp16.h>
#include <cstdint>

#define B_SZ 8192
#define L_SZ 64
#define EMB  64
#define HID  128
#define G3   384
#define OUTD 128
#define NVAL 1000

__device__ float g_tab[NVAL * G3];      // xg table, PERMUTED within 16-chunks (fp32, L2-hot)
__device__ float g_Wih_t[EMB * G3];
__device__ float g_cbias[G3];
__device__ uint32_t g_Bf[8 * 8 * 32 * 12];  // Whh fp16 B-fragments, 96KB
__device__ uint32_t g_Of[8 * 32 * 32];      // Wout fp16 B-fragments, 32KB

__device__ __forceinline__ float ftanh_fast(float x) {
    float r;
    asm("tanh.approx.f32 %0, %1;" : "=f"(r) : "f"(x));
    return r;
}
__device__ __forceinline__ float fsig_fast(float x) {
    return fmaf(0.5f, ftanh_fast(0.5f * x), 0.5f);
}
__device__ __forceinline__ uint32_t packh2(float lo, float hi) {
    __half2 h = __floats2half2_rn(lo, hi);
    return *reinterpret_cast<uint32_t*>(&h);
}
__device__ __forceinline__ void hmma(float* d, const uint32_t* a, uint32_t b0, uint32_t b1) {
    asm volatile("mma.sync.aligned.m16n8k16.row.col.f32.f16.f16.f32 "
        "{%0,%1,%2,%3}, {%4,%5,%6,%7}, {%8,%9}, {%0,%1,%2,%3};"
        : "+f"(d[0]), "+f"(d[1]), "+f"(d[2]), "+f"(d[3])
        : "r"(a[0]), "r"(a[1]), "r"(a[2]), "r"(a[3]), "r"(b0), "r"(b1));
}
__device__ __forceinline__ int pperm(int o) {
    return 4 * ((o & 7) >> 1) + (((o >> 3) & 1) << 1) + (o & 1);
}

// ---------------- prep: fragment images ----------------
__global__ void prep_kernel(const float* __restrict__ Wih, const float* __restrict__ Whh,
                            const float* __restrict__ bih, const float* __restrict__ bhh,
                            const float* __restrict__ Wout) {
    int i = blockIdx.x * blockDim.x + threadIdx.x;
    if (i < EMB * G3) { int k = i / G3, gj = i % G3; g_Wih_t[i] = Wih[gj * EMB + k]; }
    if (i < G3) g_cbias[i] = bih[i] + (i < 2 * HID ? bhh[i] : 0.0f);
    if (i < G3 * HID) {
        int gj = i / HID, k = i % HID;
        uint16_t hb = __half_as_ushort(__float2half_rn(Whh[i]));
        int gate = gj >> 7, jr = gj & 127;
        int jc = jr >> 4, nt = (jr >> 3) & 1, nl = jr & 7;
        int kc = k >> 4, kk = k & 15;
        int breg = kk >> 3, q = (kk & 7) >> 1, hs = kk & 1;
        int T = nl * 4 + q, f = gate * 2 + nt;
        int u = ((jc * 8 + kc) * 32 + T) * 12 + f * 2 + breg;
        ((uint16_t*)g_Bf)[u * 2 + hs] = hb;
    }
    if (i < OUTD * HID) {
        int o = i / HID, k = i % HID;
        uint16_t hb = __half_as_ushort(__float2half_rn(Wout[i]));
        int f = o >> 3, nl = o & 7;
        int kc = k >> 4, kk = k & 15;
        int breg = kk >> 3, q = (kk & 7) >> 1, hs = kk & 1;
        int T = nl * 4 + q;
        int u = (kc * 32 + T) * 32 + f * 2 + breg;
        ((uint16_t*)g_Of)[u * 2 + hs] = hb;
    }
}

__global__ void table_kernel(const float* __restrict__ embed) {
    __shared__ float es[EMB];
    const int v = blockIdx.x, gj = threadIdx.x;
    if (gj < EMB) es[gj] = embed[v * EMB + gj];
    __syncthreads();
    float acc = 0.0f;
    #pragma unroll 8
    for (int k = 0; k < EMB; k++) acc = fmaf(es[k], g_Wih_t[k * G3 + gj], acc);
    const int gate = gj >> 7, rest = gj & 127, chunk = rest >> 4, o = rest & 15;
    g_tab[v * G3 + gate * 128 + chunk * 16 + pperm(o)] = acc + g_cbias[gj];
}

// ---------------- GRU: N-split warp pairs, 2 warps/SMSP, named-barrier h-exchange ----------------
#define NTH 256
#define EXCH_U32 32896
#define GRU_SMEM ((EXCH_U32 + 2 * NTH * 16) * 4)   // 164352 bytes
__global__ __launch_bounds__(NTH, 1) void gru_kernel(const int* __restrict__ x,
                                                     const float* __restrict__ bhh,
                                                     const float* __restrict__ bout,
                                                     float* __restrict__ out) {
    extern __shared__ uint32_t sm[];
    uint32_t* Bs = sm;                      // 24576 u32 (96KB)
    uint32_t* Os = sm + 24576;              // 8192 u32 (32KB)
    float* bns = (float*)(sm + 32768);      // 128 floats, permuted bhh_n
    uint4* exch = (uint4*)(sm + EXCH_U32);  // 2 x 256 threads x 4 uint4
    const int tid = threadIdx.x;
    {
        uint4* d = (uint4*)sm;
        const uint4* s1 = (const uint4*)g_Bf;
        for (int i = tid; i < 6144; i += NTH) d[i] = s1[i];
        const uint4* s2 = (const uint4*)g_Of;
        for (int i = tid; i < 2048; i += NTH) d[6144 + i] = s2[i];
    }
    if (tid < 128) {
        int o = tid & 15, chunk = tid >> 4;
        bns[chunk * 16 + pperm(o)] = bhh[256 + tid];
    }
    __syncthreads();

    const int w = tid >> 5, T = tid & 31;
    const int sub = w & 1, pairid = w >> 1;       // pair shares a 16-row tile; sub splits j
    const int g = T >> 2, a4 = (T & 3) * 4;
    const int rowA = blockIdx.x * 64 + pairid * 16 + g;
    const int rowB = rowA + 8;
    const int jbase = sub * 64;                    // own j range: [jbase, jbase+64)
    const float* __restrict__ tab = g_tab;
    const float* bnsw = bns + jbase + a4;
    const uint32_t* Bsw = Bs + sub * 4 * 8 * 32 * 12;

    uint32_t A[32];
    float hp[32];                                  // fp32 h carry for OWN j's only
    #pragma unroll
    for (int i = 0; i < 32; i++) A[i] = 0u;
    #pragma unroll
    for (int i = 0; i < 32; i++) hp[i] = 0.0f;

    int idxA = x[rowA * L_SZ], idxB = x[rowB * L_SZ];
    const float* tA = tab + (size_t)idxA * G3 + jbase + a4;
    const float* tB = tab + (size_t)idxB * G3 + jbase + a4;

    // preload own chunk 0 of step 0
    float4 crA = __ldg((const float4*)(tA));
    float4 crB = __ldg((const float4*)(tB));
    float4 czA = __ldg((const float4*)(tA + 128));
    float4 czB = __ldg((const float4*)(tB + 128));
    float4 cnA = __ldg((const float4*)(tA + 256));
    float4 cnB = __ldg((const float4*)(tB + 256));

    #pragma unroll 1
    for (int t = 0; t < L_SZ; t++) {
        int idxA2 = idxA, idxB2 = idxB;
        if (t + 1 < L_SZ) {
            idxA2 = x[rowA * L_SZ + t + 1];
            idxB2 = x[rowB * L_SZ + t + 1];
        }
        uint4 AnR[4];
        #pragma unroll
        for (int jci = 0; jci < 4; jci++) {        // own 4 chunks; all reg indices static
            float4 bn4 = *(const float4*)(bnsw + jci * 16);
            float d[6][4] = {
                {crA.x, crA.y, crB.x, crB.y}, {crA.z, crA.w, crB.z, crB.w},
                {czA.x, czA.y, czB.x, czB.y}, {czA.z, czA.w, czB.z, czB.w},
                {bn4.x, bn4.y, bn4.x, bn4.y}, {bn4.z, bn4.w, bn4.z, bn4.w}
            };
            float4 xnc_A = cnA, xnc_B = cnB;
            // prefetch next own chunk (wraps into next step)
            if (jci < 3) {
                const int jn = (jci + 1) * 16;
                crA = __ldg((const float4*)(tA + jn));
                crB = __ldg((const float4*)(tB + jn));
                czA = __ldg((const float4*)(tA + 128 + jn));
                czB = __ldg((const float4*)(tB + 128 + jn));
                cnA = __ldg((const float4*)(tA + 256 + jn));
                cnB = __ldg((const float4*)(tB + 256 + jn));
            } else {
                tA = tab + (size_t)idxA2 * G3 + jbase + a4;
                tB = tab + (size_t)idxB2 * G3 + jbase + a4;
                crA = __ldg((const float4*)(tA));
                crB = __ldg((const float4*)(tB));
                czA = __ldg((const float4*)(tA + 128));
                czB = __ldg((const float4*)(tB + 128));
                cnA = __ldg((const float4*)(tA + 256));
                cnB = __ldg((const float4*)(tB + 256));
            }

            #pragma unroll
            for (int kc = 0; kc < 8; kc++) {
                const uint4* bp = (const uint4*)(Bsw + ((jci * 8 + kc) * 32 + T) * 12);
                uint4 b0 = bp[0], b1 = bp[1], b2 = bp[2];
                hmma(d[0], &A[kc * 4], b0.x, b0.y);
                hmma(d[1], &A[kc * 4], b0.z, b0.w);
                hmma(d[2], &A[kc * 4], b1.x, b1.y);
                hmma(d[3], &A[kc * 4], b1.z, b1.w);
                hmma(d[4], &A[kc * 4], b2.x, b2.y);
                hmma(d[5], &A[kc * 4], b2.z, b2.w);
            }

            float xn[8] = {xnc_A.x, xnc_A.y, xnc_B.x, xnc_B.y,
                           xnc_A.z, xnc_A.w, xnc_B.z, xnc_B.w};
            float hv[8];
            #pragma unroll
            for (int u = 0; u < 8; u++) {
                int nt = u >> 2, pos = u & 3;
                float r = fsig_fast(d[nt][pos]);
                float z = fsig_fast(d[2 + nt][pos]);
                float n = ftanh_fast(fmaf(r, d[4 + nt][pos], xn[u]));
                float h = fmaf(z, hp[jci * 8 + u] - n, n);
                hp[jci * 8 + u] = h;
                hv[u] = h;
            }
            AnR[jci] = make_uint4(packh2(hv[0], hv[1]), packh2(hv[2], hv[3]),
                                  packh2(hv[4], hv[5]), packh2(hv[6], hv[7]));
        }

        // pair h-exchange: write own 4 fragments, named barrier, read partner's 4
        {
            uint4* mine = exch + ((size_t)(t & 1) * NTH + tid) * 4;
            mine[0] = AnR[0]; mine[1] = AnR[1]; mine[2] = AnR[2]; mine[3] = AnR[3];
            asm volatile("bar.sync %0, 64;" :: "r"(1 + pairid) : "memory");
            const uint4* theirs = exch + ((size_t)(t & 1) * NTH + (tid ^ 32)) * 4;
            uint4 p0 = theirs[0], p1 = theirs[1], p2 = theirs[2], p3 = theirs[3];
            if (sub == 0) {
                A[0]  = AnR[0].x; A[1]  = AnR[0].y; A[2]  = AnR[0].z; A[3]  = AnR[0].w;
                A[4]  = AnR[1].x; A[5]  = AnR[1].y; A[6]  = AnR[1].z; A[7]  = AnR[1].w;
                A[8]  = AnR[2].x; A[9]  = AnR[2].y; A[10] = AnR[2].z; A[11] = AnR[2].w;
                A[12] = AnR[3].x; A[13] = AnR[3].y; A[14] = AnR[3].z; A[15] = AnR[3].w;
                A[16] = p0.x; A[17] = p0.y; A[18] = p0.z; A[19] = p0.w;
                A[20] = p1.x; A[21] = p1.y; A[22] = p1.z; A[23] = p1.w;
                A[24] = p2.x; A[25] = p2.y; A[26] = p2.z; A[27] = p2.w;
                A[28] = p3.x; A[29] = p3.y; A[30] = p3.z; A[31] = p3.w;
            } else {
                A[0]  = p0.x; A[1]  = p0.y; A[2]  = p0.z; A[3]  = p0.w;
                A[4]  = p1.x; A[5]  = p1.y; A[6]  = p1.z; A[7]  = p1.w;
                A[8]  = p2.x; A[9]  = p2.y; A[10] = p2.z; A[11] = p2.w;
                A[12] = p3.x; A[13] = p3.y; A[14] = p3.z; A[15] = p3.w;
                A[16] = AnR[0].x; A[17] = AnR[0].y; A[18] = AnR[0].z; A[19] = AnR[0].w;
                A[20] = AnR[1].x; A[21] = AnR[1].y; A[22] = AnR[1].z; A[23] = AnR[1].w;
                A[24] = AnR[2].x; A[25] = AnR[2].y; A[26] = AnR[2].z; A[27] = AnR[2].w;
                A[28] = AnR[3].x; A[29] = AnR[3].y; A[30] = AnR[3].z; A[31] = AnR[3].w;
            }
        }
        idxA = idxA2; idxB = idxB2;
    }

    // output projection (split: sub covers 8 of 16 f-pairs -> 4 uint4)
    float od[8][4];
    #pragma unroll
    for (int f = 0; f < 8; f++)
        #pragma unroll
        for (int p = 0; p < 4; p++) od[f][p] = 0.0f;
    #pragma unroll
    for (int kc = 0; kc < 8; kc++) {
        const uint4* op = (const uint4*)(Os + (kc * 32 + T) * 32) + sub * 4;
        #pragma unroll
        for (int f2 = 0; f2 < 4; f2++) {
            uint4 v = op[f2];
            hmma(od[f2 * 2 + 0], &A[kc * 4], v.x, v.y);
            hmma(od[f2 * 2 + 1], &A[kc * 4], v.z, v.w);
        }
    }
    const int q2 = (T & 3) * 2;
    #pragma unroll
    for (int f2 = 0; f2 < 8; f2++) {
        const int f = sub * 8 + f2;
        float2 bo = *(const float2*)(bout + f * 8 + q2);
        float2 oA = make_float2(od[f2][0] + bo.x, od[f2][1] + bo.y);
        float2 oB = make_float2(od[f2][2] + bo.x, od[f2][3] + bo.y);
        *(float2*)(out + (size_t)rowA * OUTD + f * 8 + q2) = oA;
        *(float2*)(out + (size_t)rowB * OUTD + f * 8 + q2) = oB;
    }
}

extern "C" void kernel_launch(void* const* d_in, const int* in_sizes, int n_in,
                              void* d_out, int out_size) {
    const int*   x     = (const int*)d_in[0];
    const float* embed = (const float*)d_in[1];
    const float* Wih   = (const float*)d_in[2];
    const float* Whh   = (const float*)d_in[3];
    const float* bih   = (const float*)d_in[4];
    const float* bhh   = (const float*)d_in[5];
    const float* Wout  = (const float*)d_in[6];
    const float* bout  = (const float*)d_in[7];
    float* out = (float*)d_out;

    static bool attr_done = false;
    if (!attr_done) {
        cudaFuncSetAttribute(gru_kernel, cudaFuncAttributeMaxDynamicSharedMemorySize, GRU_SMEM);
        attr_done = true;
    }

    prep_kernel<<<192, 256>>>(Wih, Whh, bih, bhh, Wout);
    table_kernel<<<NVAL, G3>>>(embed);
    gru_kernel<<<B_SZ / 64, NTH, GRU_SMEM>>>(x, bhh, bout, out);
}